// round 2
// baseline (speedup 1.0000x reference)
#include <cuda_runtime.h>
#include <cuda_bf16.h>

// Problem dims (fixed by the reference)
#define IN_F   4096
#define OUT_F  11008
#define M_DIM  (4 * 2048)     // B*S = 8192
#define N_DIM  OUT_F          // 11008
#define K_DIM  IN_F           // 4096

// Scratch: ternarized + scaled weight, fp32, [OUT_F, IN_F] row-major (K-contiguous)
__device__ float g_packed[(size_t)OUT_F * IN_F];

// ---------------------------------------------------------------------------
// Prepass: packed[o,i] = sign(w) * (|w| >= thr[o]) * scale[o]
// Bit-identical to reference's ternary*scale (fp32 throughout).
// Vectorized float4; IN_F divisible by 4.
// ---------------------------------------------------------------------------
__global__ __launch_bounds__(256) void ternarize_kernel(
    const float* __restrict__ weight,
    const float* __restrict__ scale,
    const float* __restrict__ threshold,
    float* __restrict__ packed)
{
    const int total4 = OUT_F * (IN_F / 4);
    int idx = blockIdx.x * blockDim.x + threadIdx.x;
    if (idx >= total4) return;

    const int o = idx / (IN_F / 4);
    const float t = threshold[o];
    const float s = scale[o];

    float4 w = reinterpret_cast<const float4*>(weight)[idx];
    float4 r;
    r.x = (fabsf(w.x) >= t) ? copysignf(s, w.x) : 0.0f;
    r.y = (fabsf(w.y) >= t) ? copysignf(s, w.y) : 0.0f;
    r.z = (fabsf(w.z) >= t) ? copysignf(s, w.z) : 0.0f;
    r.w = (fabsf(w.w) >= t) ? copysignf(s, w.w) : 0.0f;
    reinterpret_cast<float4*>(packed)[idx] = r;
}

// ---------------------------------------------------------------------------
// SGEMM: C[m,n] = sum_k A[m,k] * W[n,k] + bias[n]
// A: [M,K] row-major, W: [N,K] row-major (both K-contiguous -> coalesced f4 loads)
// Tiling: 128x128 block, BK=8, 256 threads, 8x8 per thread.
// All dims divide exactly; no bounds checks.
// ---------------------------------------------------------------------------
#define BM 128
#define BN 128
#define BK 8
#define TM 8
#define TN 8

__global__ __launch_bounds__(256) void sgemm_kernel(
    const float* __restrict__ A,
    const float* __restrict__ W,
    const float* __restrict__ bias,
    float* __restrict__ C)
{
    __shared__ float As[BK][BM];
    __shared__ float Ws[BK][BN];

    const int tid = threadIdx.x;
    const int bx = blockIdx.x;   // N tile
    const int by = blockIdx.y;   // M tile

    // 16x16 thread grid, each thread owns an 8x8 output micro-tile
    const int tx = tid & 15;     // N direction
    const int ty = tid >> 4;     // M direction

    // Load mapping: tile is 128 rows x 8 floats = 2 float4 per row,
    // 256 float4 total -> exactly 1 per thread.
    const int ldRow  = tid >> 1;          // 0..127
    const int ldCol4 = (tid & 1) * 4;     // 0 or 4

    const float* Aptr = A + (size_t)(by * BM + ldRow) * K_DIM + ldCol4;
    const float* Wptr = W + (size_t)(bx * BN + ldRow) * K_DIM + ldCol4;

    float acc[TM][TN];
    #pragma unroll
    for (int i = 0; i < TM; i++)
        #pragma unroll
        for (int j = 0; j < TN; j++)
            acc[i][j] = 0.0f;

    float ar[TM], wr[TN];

    for (int k0 = 0; k0 < K_DIM; k0 += BK) {
        float4 av = *reinterpret_cast<const float4*>(Aptr + k0);
        float4 wv = *reinterpret_cast<const float4*>(Wptr + k0);

        As[ldCol4 + 0][ldRow] = av.x;
        As[ldCol4 + 1][ldRow] = av.y;
        As[ldCol4 + 2][ldRow] = av.z;
        As[ldCol4 + 3][ldRow] = av.w;
        Ws[ldCol4 + 0][ldRow] = wv.x;
        Ws[ldCol4 + 1][ldRow] = wv.y;
        Ws[ldCol4 + 2][ldRow] = wv.z;
        Ws[ldCol4 + 3][ldRow] = wv.w;

        __syncthreads();

        #pragma unroll
        for (int k = 0; k < BK; k++) {
            #pragma unroll
            for (int i = 0; i < TM; i++) ar[i] = As[k][ty * TM + i];
            #pragma unroll
            for (int j = 0; j < TN; j++) wr[j] = Ws[k][tx * TN + j];
            #pragma unroll
            for (int i = 0; i < TM; i++)
                #pragma unroll
                for (int j = 0; j < TN; j++)
                    acc[i][j] = fmaf(ar[i], wr[j], acc[i][j]);
        }

        __syncthreads();
    }

    // Epilogue: add bias (per output column n), float4 stores
    const int row0 = by * BM + ty * TM;
    const int col0 = bx * BN + tx * TN;

    float4 b0 = *reinterpret_cast<const float4*>(bias + col0);
    float4 b1 = *reinterpret_cast<const float4*>(bias + col0 + 4);

    #pragma unroll
    for (int i = 0; i < TM; i++) {
        float* crow = C + (size_t)(row0 + i) * N_DIM + col0;
        float4 o0, o1;
        o0.x = acc[i][0] + b0.x;
        o0.y = acc[i][1] + b0.y;
        o0.z = acc[i][2] + b0.z;
        o0.w = acc[i][3] + b0.w;
        o1.x = acc[i][4] + b1.x;
        o1.y = acc[i][5] + b1.y;
        o1.z = acc[i][6] + b1.z;
        o1.w = acc[i][7] + b1.w;
        reinterpret_cast<float4*>(crow)[0] = o0;
        reinterpret_cast<float4*>(crow)[1] = o1;
    }
}

// ---------------------------------------------------------------------------
// kernel_launch: prepass (ternarize weights) then GEMM. Graph-capturable:
// two plain kernel launches, no sync, no allocation.
// Inputs (metadata order): input, weight, scale, threshold, bias
// ---------------------------------------------------------------------------
extern "C" void kernel_launch(void* const* d_in, const int* in_sizes, int n_in,
                              void* d_out, int out_size)
{
    const float* input     = (const float*)d_in[0];
    const float* weight    = (const float*)d_in[1];
    const float* scale     = (const float*)d_in[2];
    const float* threshold = (const float*)d_in[3];
    const float* bias      = (const float*)d_in[4];
    float* out = (float*)d_out;

    float* packed = nullptr;
    cudaGetSymbolAddress((void**)&packed, g_packed);

    // Prepass: ternarize + scale the weight
    const int total4 = OUT_F * (IN_F / 4);
    ternarize_kernel<<<(total4 + 255) / 256, 256>>>(weight, scale, threshold, packed);

    // GEMM: grid (N/128, M/128) = (86, 64)
    dim3 grid(N_DIM / BN, M_DIM / BM);
    sgemm_kernel<<<grid, 256>>>(input, packed, bias, out);
}

// round 4
// speedup vs baseline: 5.6449x; 5.6449x over previous
#include <cuda_runtime.h>
#include <cuda_bf16.h>
#include <cstdint>

// ---------------------------------------------------------------------------
// Problem dims (fixed)
// ---------------------------------------------------------------------------
#define M_DIM 8192
#define N_DIM 11008
#define K_DIM 4096

#define BM 128
#define BN 128
#define BK 32
#define KT (K_DIM / BK)      // 128
#define MT (M_DIM / BM)      // 64
#define NT (N_DIM / BN)      // 86

#define A_TILE 8192          // 128x32 bf16
#define B_TILE 8192          // 128x32 bf16
#define NSTAGE 3
#define STAGE_BYTES (2 * A_TILE + B_TILE)            // 24576
#define SMEM_TOTAL (NSTAGE * STAGE_BYTES)            // 73728

// Scratch: fragment-ordered, tile-contiguous operand images
__device__ unsigned char g_Ahi[(size_t)MT * KT * A_TILE];  // 64 MB
__device__ unsigned char g_Alo[(size_t)MT * KT * A_TILE];  // 64 MB
__device__ unsigned char g_Bt [(size_t)NT * KT * B_TILE];  // 86 MB

// ---------------------------------------------------------------------------
// helpers
// ---------------------------------------------------------------------------
__device__ __forceinline__ uint32_t smem_u32(const void* p) {
    uint32_t a;
    asm("{ .reg .u64 t; cvta.to.shared.u64 t, %1; cvt.u32.u64 %0, t; }" : "=r"(a) : "l"(p));
    return a;
}

__device__ __forceinline__ void cp16(uint32_t dst, const void* src) {
    asm volatile("cp.async.cg.shared.global [%0], [%1], 16;" :: "r"(dst), "l"(src) : "memory");
}
#define CP_COMMIT() asm volatile("cp.async.commit_group;" ::: "memory")
#define CP_WAIT1()  asm volatile("cp.async.wait_group 1;" ::: "memory")

__device__ __forceinline__ void mma16816(float* c, const uint32_t* a, const uint32_t* b) {
    asm volatile(
        "mma.sync.aligned.m16n8k16.row.col.f32.bf16.bf16.f32 "
        "{%0,%1,%2,%3}, {%4,%5,%6,%7}, {%8,%9}, {%0,%1,%2,%3};"
        : "+f"(c[0]), "+f"(c[1]), "+f"(c[2]), "+f"(c[3])
        : "r"(a[0]), "r"(a[1]), "r"(a[2]), "r"(a[3]), "r"(b[0]), "r"(b[1]));
}

__device__ __forceinline__ uint32_t pack_bf16x2(float lo, float hi) {
    __nv_bfloat162 v;
    v.x = __float2bfloat16_rn(lo);
    v.y = __float2bfloat16_rn(hi);
    return *reinterpret_cast<uint32_t*>(&v);
}

// ---------------------------------------------------------------------------
// Prepass A: split fp32 input into hi/lo bf16, fragment-ordered tiles.
// Tile inner layout: fid = (warp_m*2 + k_step)*4 + m_frag  (16 frags x 512B),
// within frag: lane*16 bytes = regs {a0,a1,a2,a3} of mma m16n8k16 A-frag.
//   reg r, half h: row16 = (l>>2) + 8*(r&1), col16 = (l&3)*2 + h + 8*(r>>1)
// One thread per 16B chunk.
// ---------------------------------------------------------------------------
__global__ __launch_bounds__(256) void prep_A(const float* __restrict__ X) {
    size_t t = (size_t)blockIdx.x * 256 + threadIdx.x;   // total = MT*KT*512
    int lane = (int)(t & 31);
    int fid  = (int)((t >> 5) & 15);
    size_t tile = t >> 9;
    int kt = (int)(tile % KT);
    int mt = (int)(tile / KT);

    int warp_m = fid >> 3, k_step = (fid >> 2) & 1, mfr = fid & 3;
    int mbase = mt * BM + warp_m * 64 + mfr * 16 + (lane >> 2);
    int kbase = kt * BK + k_step * 16 + (lane & 3) * 2;

    uint32_t hi[4], lo[4];
#pragma unroll
    for (int r = 0; r < 4; r++) {
        int m = mbase + 8 * (r & 1);
        int k = kbase + 8 * (r >> 1);
        float2 v = *reinterpret_cast<const float2*>(X + (size_t)m * K_DIM + k);
        float h0 = __bfloat162float(__float2bfloat16_rn(v.x));
        float h1 = __bfloat162float(__float2bfloat16_rn(v.y));
        hi[r] = pack_bf16x2(h0, h1);
        lo[r] = pack_bf16x2(v.x - h0, v.y - h1);
    }
    *reinterpret_cast<uint4*>(g_Ahi + t * 16) = *reinterpret_cast<uint4*>(hi);
    *reinterpret_cast<uint4*>(g_Alo + t * 16) = *reinterpret_cast<uint4*>(lo);
}

// ---------------------------------------------------------------------------
// Prepass B: ternarize weight -> bf16 {-1,0,+1}, fragment-ordered tiles.
// Tile inner layout: fid = (warp_n*2 + k_step)*2 + n_pair (16 frags-pairs x 512B)
// lane 16B = {even_b0, even_b1, odd_b0, odd_b1}; B-frag (col):
//   n = base + (l>>2) (+8 for odd frag), k = r*8 + (l&3)*2 + h
// ---------------------------------------------------------------------------
__global__ __launch_bounds__(256) void prep_B(const float* __restrict__ W,
                                              const float* __restrict__ thr) {
    size_t t = (size_t)blockIdx.x * 256 + threadIdx.x;   // total = NT*KT*512
    int lane = (int)(t & 31);
    int fid  = (int)((t >> 5) & 15);
    size_t tile = t >> 9;
    int kt = (int)(tile % KT);
    int nt = (int)(tile / KT);

    int warp_n = fid >> 2, k_step = (fid >> 1) & 1, npair = fid & 1;
    int nb = nt * BN + warp_n * 32 + npair * 16 + (lane >> 2);
    int kbase = kt * BK + k_step * 16 + (lane & 3) * 2;

    uint32_t out[4];
#pragma unroll
    for (int p = 0; p < 2; p++) {           // even / odd frag (n, n+8)
        int n = nb + p * 8;
        float tv = thr[n];
#pragma unroll
        for (int r = 0; r < 2; r++) {       // k, k+8
            float2 v = *reinterpret_cast<const float2*>(W + (size_t)n * K_DIM + kbase + r * 8);
            float t0 = (fabsf(v.x) >= tv) ? copysignf(1.0f, v.x) : 0.0f;
            float t1 = (fabsf(v.y) >= tv) ? copysignf(1.0f, v.y) : 0.0f;
            out[p * 2 + r] = pack_bf16x2(t0, t1);
        }
    }
    *reinterpret_cast<uint4*>(g_Bt + t * 16) = *reinterpret_cast<uint4*>(out);
}

// ---------------------------------------------------------------------------
// GEMM: C[m,n] = (Xhi + Xlo) @ T^T, epilogue *scale[n] + bias[n]
// 256 threads = 8 warps (2 m x 4 n), warp tile 64x32, BK=32, 3-stage cp.async
// ---------------------------------------------------------------------------
__global__ __launch_bounds__(256, 2) void gemm_kernel(const float* __restrict__ scale,
                                                      const float* __restrict__ bias,
                                                      float* __restrict__ C) {
    extern __shared__ __align__(128) unsigned char smem[];
    const uint32_t sb = smem_u32(smem);

    const int tid = threadIdx.x;
    const int wid = tid >> 5;
    const int lane = tid & 31;
    const int warp_m = wid >> 2;     // 0..1
    const int warp_n = wid & 3;      // 0..3
    const int bx = blockIdx.x;       // N tile
    const int by = blockIdx.y;       // M tile

    const unsigned char* gAh = g_Ahi + (size_t)by * KT * A_TILE;
    const unsigned char* gAl = g_Alo + (size_t)by * KT * A_TILE;
    const unsigned char* gB  = g_Bt  + (size_t)bx * KT * B_TILE;

    // stage copy: 24 KB = 1536 x 16B chunks / 256 threads = 6 per thread
    auto stage_copy = [&](int kt, int st) {
        uint32_t d = sb + st * STAGE_BYTES;
        const unsigned char* sh = gAh + (size_t)kt * A_TILE;
        const unsigned char* sl = gAl + (size_t)kt * A_TILE;
        const unsigned char* sB = gB  + (size_t)kt * B_TILE;
        cp16(d + tid * 16,                 sh + tid * 16);
        cp16(d + (tid + 256) * 16,         sh + (tid + 256) * 16);
        cp16(d + A_TILE + tid * 16,        sl + tid * 16);
        cp16(d + A_TILE + (tid + 256) * 16, sl + (tid + 256) * 16);
        cp16(d + 2 * A_TILE + tid * 16,    sB + tid * 16);
        cp16(d + 2 * A_TILE + (tid + 256) * 16, sB + (tid + 256) * 16);
    };

    float acc[4][4][4];
#pragma unroll
    for (int i = 0; i < 4; i++)
#pragma unroll
        for (int j = 0; j < 4; j++)
#pragma unroll
            for (int e = 0; e < 4; e++) acc[i][j][e] = 0.0f;

    // prologue
    stage_copy(0, 0); CP_COMMIT();
    stage_copy(1, 1); CP_COMMIT();

    int st = 0;
    for (int kt = 0; kt < KT; kt++) {
        CP_WAIT1();
        __syncthreads();

        if (kt + 2 < KT) stage_copy(kt + 2, (kt + 2) % NSTAGE);
        CP_COMMIT();

        const uint32_t aBaseHi = sb + st * STAGE_BYTES;
        const uint32_t aBaseLo = aBaseHi + A_TILE;
        const uint32_t bBase   = aBaseHi + 2 * A_TILE;

#pragma unroll
        for (int ks = 0; ks < 2; ks++) {
            uint32_t ah[4][4], al[4][4], bb[2][4];
#pragma unroll
            for (int mi = 0; mi < 4; mi++) {
                uint32_t off = (uint32_t)(((warp_m * 2 + ks) * 4 + mi) * 512 + lane * 16);
                *reinterpret_cast<uint4*>(ah[mi]) = *reinterpret_cast<const uint4*>(smem + st * STAGE_BYTES + off);
                *reinterpret_cast<uint4*>(al[mi]) = *reinterpret_cast<const uint4*>(smem + st * STAGE_BYTES + A_TILE + off);
            }
#pragma unroll
            for (int np = 0; np < 2; np++) {
                uint32_t off = (uint32_t)(((warp_n * 2 + ks) * 2 + np) * 512 + lane * 16);
                *reinterpret_cast<uint4*>(bb[np]) = *reinterpret_cast<const uint4*>(smem + st * STAGE_BYTES + 2 * A_TILE + off);
            }
#pragma unroll
            for (int mi = 0; mi < 4; mi++)
#pragma unroll
                for (int ni = 0; ni < 4; ni++)
                    mma16816(acc[mi][ni], ah[mi], &bb[ni >> 1][(ni & 1) * 2]);
#pragma unroll
            for (int mi = 0; mi < 4; mi++)
#pragma unroll
                for (int ni = 0; ni < 4; ni++)
                    mma16816(acc[mi][ni], al[mi], &bb[ni >> 1][(ni & 1) * 2]);
        }
        (void)aBaseHi; (void)aBaseLo; (void)bBase;
        st = (st + 1) % NSTAGE;
        __syncthreads();
    }

    // epilogue: C-frag: c0,c1 -> row (l>>2), cols (l&3)*2 + {0,1}; c2,c3 -> row+8
    const int m0 = by * BM + warp_m * 64;
    const int n0 = bx * BN + warp_n * 32;
    const int r = lane >> 2;
    const int cp = (lane & 3) * 2;

#pragma unroll
    for (int ni = 0; ni < 4; ni++) {
        int n = n0 + ni * 8 + cp;
        float2 sc = *reinterpret_cast<const float2*>(scale + n);
        float2 bi = *reinterpret_cast<const float2*>(bias + n);
#pragma unroll
        for (int mi = 0; mi < 4; mi++) {
            int m = m0 + mi * 16 + r;
            float2 o0, o1;
            o0.x = fmaf(acc[mi][ni][0], sc.x, bi.x);
            o0.y = fmaf(acc[mi][ni][1], sc.y, bi.y);
            o1.x = fmaf(acc[mi][ni][2], sc.x, bi.x);
            o1.y = fmaf(acc[mi][ni][3], sc.y, bi.y);
            *reinterpret_cast<float2*>(C + (size_t)m * N_DIM + n) = o0;
            *reinterpret_cast<float2*>(C + (size_t)(m + 8) * N_DIM + n) = o1;
        }
    }
}

// ---------------------------------------------------------------------------
// kernel_launch — 3 kernels, graph-capturable, no allocation
// Inputs: input, weight, scale, threshold, bias
// ---------------------------------------------------------------------------
extern "C" void kernel_launch(void* const* d_in, const int* in_sizes, int n_in,
                              void* d_out, int out_size) {
    const float* input     = (const float*)d_in[0];
    const float* weight    = (const float*)d_in[1];
    const float* scale     = (const float*)d_in[2];
    const float* threshold = (const float*)d_in[3];
    const float* bias      = (const float*)d_in[4];
    float* out = (float*)d_out;

    static bool attr_set = false;
    cudaFuncSetAttribute(gemm_kernel, cudaFuncAttributeMaxDynamicSharedMemorySize, SMEM_TOTAL);
    (void)attr_set;

    prep_A<<<(int)(((size_t)MT * KT * 512) / 256), 256>>>(input);
    prep_B<<<(int)(((size_t)NT * KT * 512) / 256), 256>>>(weight, threshold);

    dim3 grid(NT, MT);
    gemm_kernel<<<grid, 256, SMEM_TOTAL>>>(scale, bias, out);
}